// round 1
// baseline (speedup 1.0000x reference)
#include <cuda_runtime.h>

#define BB 128
#define TT 4096
#define NN 32
#define FULL 0xffffffffu

// Scratch tapes for scaled forward/backward messages (ratio-invariant scale).
__device__ float g_a[(size_t)BB * TT * NN];
__device__ float g_b[(size_t)BB * TT * NN];

// ---------------------------------------------------------------------------
// Kernel 1: forward and backward recursions, one warp per chain.
//   blocks [0, BB)      : forward  pass for batch = blockIdx.x
//   blocks [BB, 2*BB)   : backward pass for batch = blockIdx.x - BB
// Lane = state. Probability-domain recursion with per-step rescale by lane-0
// value (scale cancels in the final ratio), so no log/lse on the critical path.
// ---------------------------------------------------------------------------
__global__ void __launch_bounds__(32, 32)
fb_kernel(const float* __restrict__ pots,
          const int*   __restrict__ lengths,
          const float* __restrict__ trans)
{
    const int lane = threadIdx.x;
    const int blk  = blockIdx.x;
    const bool is_fwd = (blk < BB);
    const int b = is_fwd ? blk : blk - BB;

    const int len = lengths[b];
    const float* pot = pots + (size_t)b * TT * NN;

    float E[NN];

    if (is_fwd) {
        // lane j holds exp(trans[:, j])
        #pragma unroll
        for (int i = 0; i < NN; i++) E[i] = __expf(trans[i * NN + lane]);

        float* A = g_a + (size_t)b * TT * NN;

        // t = 0 : a = exp(pot_0)
        float a = __expf(pot[lane]);
        A[lane] = a;

        // prefetch pot for t = 1 (always in-bounds since TT >= 2)
        float potn = pot[NN + lane];

        for (int t = 1; t < len; ++t) {
            float P = __expf(potn);
            int tn = (t + 1 < TT) ? (t + 1) : t;
            potn = pot[(size_t)tn * NN + lane];   // prefetch next step

            float acc0 = 0.f, acc1 = 0.f, acc2 = 0.f, acc3 = 0.f;
            float r = 0.f;
            #pragma unroll
            for (int i = 0; i < NN; i += 4) {
                float v0 = __shfl_sync(FULL, a, i + 0);
                float v1 = __shfl_sync(FULL, a, i + 1);
                float v2 = __shfl_sync(FULL, a, i + 2);
                float v3 = __shfl_sync(FULL, a, i + 3);
                if (i == 0) r = __frcp_rn(v0);    // rescale factor, off critical path
                acc0 = fmaf(v0, E[i + 0], acc0);
                acc1 = fmaf(v1, E[i + 1], acc1);
                acc2 = fmaf(v2, E[i + 2], acc2);
                acc3 = fmaf(v3, E[i + 3], acc3);
            }
            float s = (acc0 + acc1) + (acc2 + acc3);
            a = s * r * P;
            A[(size_t)t * NN + lane] = a;
        }
    } else {
        // lane i holds exp(trans[i, :])
        #pragma unroll
        for (int j = 0; j < NN; j++) E[j] = __expf(trans[lane * NN + j]);

        float* Bv = g_b + (size_t)b * TT * NN;

        // t = len-1 : beta = 0 (log) -> b = 1 (prob)
        float bv = 1.0f;
        Bv[(size_t)(len - 1) * NN + lane] = 1.0f;

        // step t consumes pot_t, produces b_{t-1}
        float potn = pot[(size_t)(len - 1) * NN + lane];

        for (int t = len - 1; t >= 1; --t) {
            float P = __expf(potn);
            int tn = (t >= 2) ? (t - 1) : 1;
            potn = pot[(size_t)tn * NN + lane];   // prefetch next step

            float u = bv * P;

            float acc0 = 0.f, acc1 = 0.f, acc2 = 0.f, acc3 = 0.f;
            float r = 0.f;
            #pragma unroll
            for (int j = 0; j < NN; j += 4) {
                float v0 = __shfl_sync(FULL, u, j + 0);
                float v1 = __shfl_sync(FULL, u, j + 1);
                float v2 = __shfl_sync(FULL, u, j + 2);
                float v3 = __shfl_sync(FULL, u, j + 3);
                if (j == 0) r = __frcp_rn(v0);
                acc0 = fmaf(v0, E[j + 0], acc0);
                acc1 = fmaf(v1, E[j + 1], acc1);
                acc2 = fmaf(v2, E[j + 2], acc2);
                acc3 = fmaf(v3, E[j + 3], acc3);
            }
            float s = (acc0 + acc1) + (acc2 + acc3);
            bv = s * r;
            Bv[(size_t)(t - 1) * NN + lane] = bv;
        }
    }
}

// ---------------------------------------------------------------------------
// Kernel 2: combine. One block per batch. Each thread handles strided t;
// p_t(y_t) = a_y * b_y / sum_k a_k b_k (all per-t scales cancel).
// sum_k p = 1 exactly, so denominator of dice uses 2*len.
// ---------------------------------------------------------------------------
__global__ void __launch_bounds__(256)
combine_kernel(const int* __restrict__ y_true,
               const int* __restrict__ lengths,
               float*     __restrict__ out)
{
    const int b   = blockIdx.x;
    const int tid = threadIdx.x;
    const int len = lengths[b];

    const float* Ab = g_a + (size_t)b * TT * NN;
    const float* Bb = g_b + (size_t)b * TT * NN;
    const int*   Yb = y_true + (size_t)b * TT;

    float part = 0.f;
    for (int t = tid; t < len; t += 256) {
        const float4* A4 = reinterpret_cast<const float4*>(Ab + (size_t)t * NN);
        const float4* B4 = reinterpret_cast<const float4*>(Bb + (size_t)t * NN);
        float s = 0.f;
        #pragma unroll
        for (int q = 0; q < 8; q++) {
            float4 av = A4[q];
            float4 bv = B4[q];
            s += av.x * bv.x + av.y * bv.y + av.z * bv.z + av.w * bv.w;
        }
        int y = Yb[t];
        float py = Ab[(size_t)t * NN + y] * Bb[(size_t)t * NN + y];
        part += __fdividef(py, s);
    }

    __shared__ float red[256];
    red[tid] = part;
    __syncthreads();
    #pragma unroll
    for (int off = 128; off > 0; off >>= 1) {
        if (tid < off) red[tid] += red[tid + off];
        __syncthreads();
    }
    if (tid == 0) {
        float inter = red[0];
        float flen  = (float)len;
        float dice  = (2.0f * inter + 1.0f) / (2.0f * flen + 1.0f);
        out[b] = 1.0f - dice;
    }
}

// ---------------------------------------------------------------------------
extern "C" void kernel_launch(void* const* d_in, const int* in_sizes, int n_in,
                              void* d_out, int out_size)
{
    const float* pots    = (const float*)d_in[0];   // [B,T,N] fp32
    const int*   y_true  = (const int*)  d_in[1];   // [B,T] int32
    const int*   lengths = (const int*)  d_in[2];   // [B] int32
    const float* trans   = (const float*)d_in[3];   // [N,N] fp32
    float* out = (float*)d_out;                     // [B] fp32

    fb_kernel<<<2 * BB, 32>>>(pots, lengths, trans);
    combine_kernel<<<BB, 256>>>(y_true, lengths, out);
}